// round 1
// baseline (speedup 1.0000x reference)
#include <cuda_runtime.h>

// WarpImage: bilinear warp of image [C=32, H=1024, W=2048] by flow [2, H, W].
// out[c,h,w] = sum of 4 bilinear taps of image[c] at (w + flow[0,h,w], h + flow[1,h,w]),
// out-of-bounds taps contribute BORDER_VALUE = 0.

#define CC 32
#define HH 1024
#define WW 2048
#define HWSZ (HH * WW)

__global__ __launch_bounds__(256) void warp_image_kernel(
    const float* __restrict__ image,
    const float* __restrict__ flow,
    float* __restrict__ out)
{
    int idx = blockIdx.x * blockDim.x + threadIdx.x;
    if (idx >= HWSZ) return;

    int w = idx & (WW - 1);
    int h = idx >> 11;   // idx / WW, WW = 2048 = 2^11

    float u = (float)w + __ldg(flow + idx);
    float v = (float)h + __ldg(flow + HWSZ + idx);

    float u0f = floorf(u);
    float v0f = floorf(v);
    float wu = u - u0f;
    float wv = v - v0f;

    int u0 = (int)u0f;
    int v0 = (int)v0f;
    int u1 = u0 + 1;
    int v1 = v0 + 1;

    bool vu0 = (u0 >= 0) && (u0 <= WW - 1);
    bool vu1 = (u1 >= 0) && (u1 <= WW - 1);
    bool vv0 = (v0 >= 0) && (v0 <= HH - 1);
    bool vv1 = (v1 >= 0) && (v1 <= HH - 1);

    int u0c = min(max(u0, 0), WW - 1);
    int u1c = min(max(u1, 0), WW - 1);
    int v0c = min(max(v0, 0), HH - 1);
    int v1c = min(max(v1, 0), HH - 1);

    float w00 = (1.0f - wu) * (1.0f - wv); if (!(vu0 && vv0)) w00 = 0.0f;
    float w10 = wu * (1.0f - wv);          if (!(vu1 && vv0)) w10 = 0.0f;
    float w01 = (1.0f - wu) * wv;          if (!(vu0 && vv1)) w01 = 0.0f;
    float w11 = wu * wv;                   if (!(vu1 && vv1)) w11 = 0.0f;

    int o00 = v0c * WW + u0c;
    int o10 = v0c * WW + u1c;
    int o01 = v1c * WW + u0c;
    int o11 = v1c * WW + u1c;

    #pragma unroll
    for (int c = 0; c < CC; c++) {
        const float* img = image + c * HWSZ;
        float g = w00 * __ldg(img + o00)
                + w10 * __ldg(img + o10)
                + w01 * __ldg(img + o01)
                + w11 * __ldg(img + o11);
        out[c * HWSZ + idx] = g;
    }
}

extern "C" void kernel_launch(void* const* d_in, const int* in_sizes, int n_in,
                              void* d_out, int out_size)
{
    const float* image = (const float*)d_in[0];
    const float* flow  = (const float*)d_in[1];
    float* out = (float*)d_out;

    int threads = 256;
    int blocks = (HWSZ + threads - 1) / threads;
    warp_image_kernel<<<blocks, threads>>>(image, flow, out);
}

// round 2
// speedup vs baseline: 1.2419x; 1.2419x over previous
#include <cuda_runtime.h>

// WarpImage: bilinear warp of image [C=32, H=1024, W=2048] by flow [2, H, W].
// out[c,h,w] = 4-tap bilinear sample of image[c] at (w + flow[0,h,w], h + flow[1,h,w]),
// out-of-bounds taps contribute 0.
//
// R2: 2D tiling (32x8 pixel tiles) so the per-block gather footprint fits L1,
// cutting the ~2.5x L2 redundancy seen in R1's profile.

#define CC 32
#define HH 1024
#define WW 2048
#define HWSZ (HH * WW)

__global__ __launch_bounds__(256) void warp_image_kernel(
    const float* __restrict__ image,
    const float* __restrict__ flow,
    float* __restrict__ out)
{
    // Block covers a 32-wide x 8-tall tile. Warp = one row of the tile
    // (threadIdx.y fixed per warp) -> stores are single-line coalesced.
    int w = blockIdx.x * 32 + threadIdx.x;
    int h = blockIdx.y * 8 + threadIdx.y;
    int idx = h * WW + w;

    float u = (float)w + __ldg(flow + idx);
    float v = (float)h + __ldg(flow + HWSZ + idx);

    float u0f = floorf(u);
    float v0f = floorf(v);
    float wu = u - u0f;
    float wv = v - v0f;

    int u0 = (int)u0f;
    int v0 = (int)v0f;
    int u1 = u0 + 1;
    int v1 = v0 + 1;

    bool vu0 = (u0 >= 0) && (u0 <= WW - 1);
    bool vu1 = (u1 >= 0) && (u1 <= WW - 1);
    bool vv0 = (v0 >= 0) && (v0 <= HH - 1);
    bool vv1 = (v1 >= 0) && (v1 <= HH - 1);

    int u0c = min(max(u0, 0), WW - 1);
    int u1c = min(max(u1, 0), WW - 1);
    int v0c = min(max(v0, 0), HH - 1);
    int v1c = min(max(v1, 0), HH - 1);

    float w00 = (1.0f - wu) * (1.0f - wv); if (!(vu0 && vv0)) w00 = 0.0f;
    float w10 = wu * (1.0f - wv);          if (!(vu1 && vv0)) w10 = 0.0f;
    float w01 = (1.0f - wu) * wv;          if (!(vu0 && vv1)) w01 = 0.0f;
    float w11 = wu * wv;                   if (!(vu1 && vv1)) w11 = 0.0f;

    int o00 = v0c * WW + u0c;
    int o10 = v0c * WW + u1c;
    int o01 = v1c * WW + u0c;
    int o11 = v1c * WW + u1c;

    #pragma unroll
    for (int c = 0; c < CC; c++) {
        const float* img = image + c * HWSZ;
        float g = w00 * __ldg(img + o00)
                + w10 * __ldg(img + o10)
                + w01 * __ldg(img + o01)
                + w11 * __ldg(img + o11);
        out[c * HWSZ + idx] = g;
    }
}

extern "C" void kernel_launch(void* const* d_in, const int* in_sizes, int n_in,
                              void* d_out, int out_size)
{
    const float* image = (const float*)d_in[0];
    const float* flow  = (const float*)d_in[1];
    float* out = (float*)d_out;

    dim3 block(32, 8);
    dim3 grid(WW / 32, HH / 8);
    warp_image_kernel<<<grid, block>>>(image, flow, out);
}